// round 1
// baseline (speedup 1.0000x reference)
#include <cuda_runtime.h>
#include <cstdint>

#define NNODES 10000
#define NEDGES 160000
#define BATCH  32
#define FIN    64
#define KPOLY  5
#define FOUT   128
#define NPOOL  (NNODES / 4)
#define TERM_SZ ((size_t)BATCH * NNODES * FIN)

// ---------------- static device scratch (no allocations allowed) ----------------
__device__ float g_T[4 * (size_t)BATCH * NNODES * FIN];   // terms T1..T4 (T0 == x)
__device__ int   g_count[NNODES];
__device__ int   g_cursor[NNODES];
__device__ int   g_row_start[NNODES + 1];
__device__ int   g_csr_col[NEDGES];
__device__ float g_csr_val[NEDGES];

// ---------------- CSR build: histogram -> scan -> permuting scatter -------------
__global__ void k_zero_counts() {
    int i = blockIdx.x * blockDim.x + threadIdx.x;
    if (i < NNODES) g_count[i] = 0;
}

__global__ void k_count(const int* __restrict__ rows) {
    int e = blockIdx.x * blockDim.x + threadIdx.x;
    if (e < NEDGES) atomicAdd(&g_count[rows[e]], 1);
}

__global__ void k_scan() {
    const int T = 256;
    const int PER = (NNODES + T - 1) / T;  // 40
    int t = threadIdx.x;
    int base = t * PER;
    int sum = 0;
    for (int i = 0; i < PER; i++) {
        int idx = base + i;
        if (idx < NNODES) sum += g_count[idx];
    }
    __shared__ int sc[T];
    sc[t] = sum;
    __syncthreads();
    for (int d = 1; d < T; d <<= 1) {
        int v = (t >= d) ? sc[t - d] : 0;
        __syncthreads();
        sc[t] += v;
        __syncthreads();
    }
    int run = sc[t] - sum;  // exclusive prefix
    for (int i = 0; i < PER; i++) {
        int idx = base + i;
        if (idx < NNODES) {
            g_row_start[idx] = run;
            g_cursor[idx] = run;
            run += g_count[idx];
        }
    }
    if (t == T - 1) g_row_start[NNODES] = run;
}

__global__ void k_scatter(const int* __restrict__ rows, const int* __restrict__ cols,
                          const float* __restrict__ vals) {
    int e = blockIdx.x * blockDim.x + threadIdx.x;
    if (e < NEDGES) {
        int r = rows[e];
        int p = atomicAdd(&g_cursor[r], 1);
        g_csr_col[p] = cols[e];
        g_csr_val[p] = vals[e];
    }
}

// ---------------- gather SpMM (Chebyshev step) ----------------------------------
// out_t  = L*Tin                        if prev_t == -2
// out_t  = 2*L*Tin - Tprev              otherwise (prev_t == -1 -> x, >=0 -> g_T)
__global__ __launch_bounds__(256) void k_spmm(const float* __restrict__ x,
                                              int in_t, int out_t, int prev_t) {
    int w = (blockIdx.x * 256 + threadIdx.x) >> 5;
    if (w >= BATCH * NNODES) return;
    int b = w / NNODES;
    int r = w - b * NNODES;
    int lane = threadIdx.x & 31;

    const float* Tin = (in_t < 0) ? x : (g_T + (size_t)in_t * TERM_SZ);
    const float* base = Tin + (size_t)b * NNODES * FIN;

    int s = g_row_start[r];
    int e = g_row_start[r + 1];
    float a0 = 0.f, a1 = 0.f;
    for (int j = s; j < e; j++) {
        int   c = g_csr_col[j];
        float v = g_csr_val[j];
        const float* src = base + (size_t)c * FIN;
        a0 += v * __ldg(src + lane);
        a1 += v * __ldg(src + lane + 32);
    }
    size_t o = ((size_t)b * NNODES + r) * FIN;
    if (prev_t >= -1) {
        const float* Tp = (prev_t < 0) ? x : (g_T + (size_t)prev_t * TERM_SZ);
        a0 = 2.f * a0 - Tp[o + lane];
        a1 = 2.f * a1 - Tp[o + lane + 32];
    }
    float* dst = g_T + (size_t)out_t * TERM_SZ + o;
    dst[lane] = a0;
    dst[lane + 32] = a1;
}

// ---------------- fused GEMM + bias + ReLU + maxpool4 ---------------------------
// out[b, n/4, fo] = maxpool4_n( relu( sum_{k,f} T_k[b,n,f] * W[f*5+k, fo] + bias[fo] ) )
// Block tile: 64 nodes x 128 fo, 256 threads, thread tile 4x8 (the 4 rows are one
// pool group, so pooling happens entirely in registers).
__global__ __launch_bounds__(256) void k_gemm(const float* __restrict__ x,
                                              const float* __restrict__ W,
                                              const float* __restrict__ bias,
                                              float* __restrict__ out) {
    __shared__ float As[32 * 68];    // As[kf*68 + m], padded for conflicts/alignment
    __shared__ float Ws[32 * 128];   // Ws[kf*128 + fo]

    int tid = threadIdx.x;
    int b = blockIdx.y;
    int n0 = blockIdx.x * 64;
    int tm = tid >> 4;   // 0..15 -> rows tm*4 .. tm*4+3
    int tn = tid & 15;   // 0..15 -> cols tn*8 .. tn*8+7

    float acc[4][8];
#pragma unroll
    for (int i = 0; i < 4; i++)
#pragma unroll
        for (int j = 0; j < 8; j++) acc[i][j] = 0.f;

#pragma unroll
    for (int kk = 0; kk < KPOLY; kk++) {
        const float* Tk = (kk == 0) ? x : (g_T + (size_t)(kk - 1) * TERM_SZ);
        const float* Abase = Tk + ((size_t)b * NNODES + n0) * FIN;
#pragma unroll
        for (int half = 0; half < 2; half++) {
            // load A tile: 64 rows x 32 f, transposed into As[kf][m]
#pragma unroll
            for (int i = 0; i < 2; i++) {
                int q = tid + 256 * i;       // 0..511 float4s
                int row = q >> 3;            // 0..63
                int f4 = q & 7;              // 0..7 (each = 4 floats of f)
                float4 v = make_float4(0.f, 0.f, 0.f, 0.f);
                if (n0 + row < NNODES)
                    v = *(const float4*)(Abase + (size_t)row * FIN + half * 32 + f4 * 4);
                As[(f4 * 4 + 0) * 68 + row] = v.x;
                As[(f4 * 4 + 1) * 68 + row] = v.y;
                As[(f4 * 4 + 2) * 68 + row] = v.z;
                As[(f4 * 4 + 3) * 68 + row] = v.w;
            }
            // load W tile: 32 f rows (global row = (half*32+f)*5 + kk) x 128 fo
#pragma unroll
            for (int i = 0; i < 4; i++) {
                int q = tid + 256 * i;       // 0..1023 float4s
                int f = q >> 5;              // 0..31
                int c4 = q & 31;             // 0..31
                int grow = (half * 32 + f) * KPOLY + kk;
                *(float4*)(Ws + f * 128 + c4 * 4) =
                    *(const float4*)(W + (size_t)grow * FOUT + c4 * 4);
            }
            __syncthreads();
#pragma unroll
            for (int kf = 0; kf < 32; kf++) {
                float4 a  = *(const float4*)(As + kf * 68 + tm * 4);
                float4 b0 = *(const float4*)(Ws + kf * 128 + tn * 8);
                float4 b1 = *(const float4*)(Ws + kf * 128 + tn * 8 + 4);
                float av[4] = {a.x, a.y, a.z, a.w};
                float bv[8] = {b0.x, b0.y, b0.z, b0.w, b1.x, b1.y, b1.z, b1.w};
#pragma unroll
                for (int i = 0; i < 4; i++)
#pragma unroll
                    for (int j = 0; j < 8; j++)
                        acc[i][j] = fmaf(av[i], bv[j], acc[i][j]);
            }
            __syncthreads();
        }
    }

    // epilogue: maxpool over the thread's 4 rows, +bias, ReLU, write pooled row
    int nf = n0 + tm * 4;
    if (nf < NNODES) {
        int pn = nf >> 2;
        float* op = out + ((size_t)b * NPOOL + pn) * FOUT + tn * 8;
        float res[8];
#pragma unroll
        for (int j = 0; j < 8; j++) {
            float m = fmaxf(fmaxf(acc[0][j], acc[1][j]), fmaxf(acc[2][j], acc[3][j]));
            res[j] = fmaxf(m + __ldg(bias + tn * 8 + j), 0.f);
        }
        *(float4*)op       = make_float4(res[0], res[1], res[2], res[3]);
        *(float4*)(op + 4) = make_float4(res[4], res[5], res[6], res[7]);
    }
}

// ---------------- launch ---------------------------------------------------------
extern "C" void kernel_launch(void* const* d_in, const int* in_sizes, int n_in,
                              void* d_out, int out_size) {
    const float* x    = (const float*)d_in[0];
    const int*   rows = (const int*)d_in[1];
    const int*   cols = (const int*)d_in[2];
    const float* vals = (const float*)d_in[3];
    const float* W    = (const float*)d_in[4];
    const float* bias = (const float*)d_in[5];
    float* out = (float*)d_out;

    // CSR build (deterministic work; scatter order immaterial up to fp rounding)
    k_zero_counts<<<(NNODES + 255) / 256, 256>>>();
    k_count<<<(NEDGES + 255) / 256, 256>>>(rows);
    k_scan<<<1, 256>>>();
    k_scatter<<<(NEDGES + 255) / 256, 256>>>(rows, cols, vals);

    // Chebyshev recurrence: T1 = L x ; Tk = 2 L T(k-1) - T(k-2)
    const int spmm_blocks = (BATCH * NNODES) / 8;  // 1 warp per (row, batch)
    k_spmm<<<spmm_blocks, 256>>>(x, -1, 0, -2);    // T1 = L x
    k_spmm<<<spmm_blocks, 256>>>(x,  0, 1, -1);    // T2 = 2 L T1 - x
    k_spmm<<<spmm_blocks, 256>>>(x,  1, 2,  0);    // T3 = 2 L T2 - T1
    k_spmm<<<spmm_blocks, 256>>>(x,  2, 3,  1);    // T4 = 2 L T3 - T2

    // fused projection + bias + relu + pool
    dim3 grid((NNODES + 63) / 64, BATCH);
    k_gemm<<<grid, 256>>>(x, W, bias, out);
}

// round 3
// speedup vs baseline: 1.9858x; 1.9858x over previous
#include <cuda_runtime.h>
#include <cstdint>

#define NNODES 10000
#define NEDGES 160000
#define BATCH  32
#define FIN    64
#define KPOLY  5
#define FOUT   128
#define NPOOL  (NNODES / 4)
#define TERM_SZ ((size_t)BATCH * NNODES * FIN)

// ---------------- static device scratch (no allocations allowed) ----------------
__device__ float g_T[4 * (size_t)BATCH * NNODES * FIN];   // terms T1..T4 (T0 == x)
__device__ float g_Wt[KPOLY * FOUT * FIN];                // W transposed: [k][fo][f]
__device__ int   g_count[NNODES];
__device__ int   g_cursor[NNODES];
__device__ int   g_row_start[NNODES + 1];
__device__ int   g_csr_col[NEDGES];
__device__ float g_csr_val[NEDGES];

// ---------------- CSR build: histogram -> scan -> permuting scatter -------------
__global__ void k_zero_counts() {
    int i = blockIdx.x * blockDim.x + threadIdx.x;
    if (i < NNODES) g_count[i] = 0;
}
__global__ void k_count(const int* __restrict__ rows) {
    int e = blockIdx.x * blockDim.x + threadIdx.x;
    if (e < NEDGES) atomicAdd(&g_count[rows[e]], 1);
}
__global__ void k_scan() {
    const int T = 256;
    const int PER = (NNODES + T - 1) / T;
    int t = threadIdx.x;
    int base = t * PER;
    int sum = 0;
    for (int i = 0; i < PER; i++) {
        int idx = base + i;
        if (idx < NNODES) sum += g_count[idx];
    }
    __shared__ int sc[T];
    sc[t] = sum;
    __syncthreads();
    for (int d = 1; d < T; d <<= 1) {
        int v = (t >= d) ? sc[t - d] : 0;
        __syncthreads();
        sc[t] += v;
        __syncthreads();
    }
    int run = sc[t] - sum;
    for (int i = 0; i < PER; i++) {
        int idx = base + i;
        if (idx < NNODES) {
            g_row_start[idx] = run;
            g_cursor[idx] = run;
            run += g_count[idx];
        }
    }
    if (t == T - 1) g_row_start[NNODES] = run;
}
__global__ void k_scatter(const int* __restrict__ rows, const int* __restrict__ cols,
                          const float* __restrict__ vals) {
    int e = blockIdx.x * blockDim.x + threadIdx.x;
    if (e < NEDGES) {
        int r = rows[e];
        int p = atomicAdd(&g_cursor[r], 1);
        g_csr_col[p] = cols[e];
        g_csr_val[p] = vals[e];
    }
}

// weight transpose: g_Wt[k][fo][f] = W[f*5+k][fo]
__global__ void k_wt(const float* __restrict__ W) {
    int i = blockIdx.x * blockDim.x + threadIdx.x;
    if (i < KPOLY * FOUT * FIN) {
        int k = i / (FOUT * FIN);
        int r = i - k * FOUT * FIN;
        int fo = r / FIN;
        int f = r - fo * FIN;
        g_Wt[i] = W[(f * KPOLY + k) * FOUT + fo];
    }
}

// ---------------- gather SpMM (Chebyshev step), unroll-4 for MLP -----------------
__global__ __launch_bounds__(256) void k_spmm(const float* __restrict__ x,
                                              int in_t, int out_t, int prev_t) {
    int w = (blockIdx.x * 256 + threadIdx.x) >> 5;
    if (w >= BATCH * NNODES) return;
    int b = w / NNODES;
    int r = w - b * NNODES;
    int lane = threadIdx.x & 31;

    const float* Tin = (in_t < 0) ? x : (g_T + (size_t)in_t * TERM_SZ);
    const float* base = Tin + (size_t)b * NNODES * FIN;

    int s = g_row_start[r];
    int e = g_row_start[r + 1];
    float a0 = 0.f, a1 = 0.f;
    int j = s;
    for (; j + 3 < e; j += 4) {
        int   c0 = g_csr_col[j],     c1 = g_csr_col[j + 1];
        int   c2 = g_csr_col[j + 2], c3 = g_csr_col[j + 3];
        float v0 = g_csr_val[j],     v1 = g_csr_val[j + 1];
        float v2 = g_csr_val[j + 2], v3 = g_csr_val[j + 3];
        const float* s0 = base + (size_t)c0 * FIN;
        const float* s1 = base + (size_t)c1 * FIN;
        const float* s2 = base + (size_t)c2 * FIN;
        const float* s3 = base + (size_t)c3 * FIN;
        float x00 = __ldg(s0 + lane),      x01 = __ldg(s0 + lane + 32);
        float x10 = __ldg(s1 + lane),      x11 = __ldg(s1 + lane + 32);
        float x20 = __ldg(s2 + lane),      x21 = __ldg(s2 + lane + 32);
        float x30 = __ldg(s3 + lane),      x31 = __ldg(s3 + lane + 32);
        a0 = fmaf(v0, x00, a0); a1 = fmaf(v0, x01, a1);
        a0 = fmaf(v1, x10, a0); a1 = fmaf(v1, x11, a1);
        a0 = fmaf(v2, x20, a0); a1 = fmaf(v2, x21, a1);
        a0 = fmaf(v3, x30, a0); a1 = fmaf(v3, x31, a1);
    }
    for (; j < e; j++) {
        int   c = g_csr_col[j];
        float v = g_csr_val[j];
        const float* src = base + (size_t)c * FIN;
        a0 = fmaf(v, __ldg(src + lane), a0);
        a1 = fmaf(v, __ldg(src + lane + 32), a1);
    }
    size_t o = ((size_t)b * NNODES + r) * FIN;
    if (prev_t >= -1) {
        const float* Tp = (prev_t < 0) ? x : (g_T + (size_t)prev_t * TERM_SZ);
        a0 = 2.f * a0 - Tp[o + lane];
        a1 = 2.f * a1 - Tp[o + lane + 32];
    }
    float* dst = g_T + (size_t)out_t * TERM_SZ + o;
    dst[lane] = a0;
    dst[lane + 32] = a1;
}

// ---------------- mma.sync tf32 projection + bias + ReLU + maxpool4 -------------
// CTA: 128 nodes x 128 fo. 8 warps (4x2), warp tile 32x64. K = 320 in 10 chunks
// of 32, cp.async double-buffered. Smem rows padded to 36 floats (conflict-free
// fragment loads AND 16B-aligned cp.async: 36 floats = 144 B = 9*16 B).
#define KCH    32
#define ASTRIDE 36
#define STAGE_FLOATS (128 * ASTRIDE)                    // per matrix per stage
#define SMEM_FLOATS  (2 * 2 * STAGE_FLOATS)             // 2 stages x (A, B)
#define SMEM_BYTES   (SMEM_FLOATS * 4)                  // 73728

__device__ __forceinline__ void mma_tf32_16x8x8(float* d, const uint32_t* a,
                                                uint32_t b0, uint32_t b1) {
    asm volatile(
        "mma.sync.aligned.m16n8k8.row.col.f32.tf32.tf32.f32 "
        "{%0,%1,%2,%3}, {%4,%5,%6,%7}, {%8,%9}, {%0,%1,%2,%3};"
        : "+f"(d[0]), "+f"(d[1]), "+f"(d[2]), "+f"(d[3])
        : "r"(a[0]), "r"(a[1]), "r"(a[2]), "r"(a[3]), "r"(b0), "r"(b1));
}

// issue cp.async for one 128x32 chunk into [dst]; rows >= max_rows zero-filled
__device__ __forceinline__ void load_chunk(float* dst, const float* __restrict__ src,
                                           int max_rows) {
    int t = threadIdx.x;
#pragma unroll
    for (int i = 0; i < 4; i++) {
        int q = t + 256 * i;           // 0..1023 16B ops
        int row = q >> 3;              // 0..127
        int f4 = q & 7;                // 0..7
        uint32_t daddr;
        asm("{ .reg .u64 tt; cvta.to.shared.u64 tt, %1; cvt.u32.u64 %0, tt; }"
            : "=r"(daddr) : "l"(dst + row * ASTRIDE + f4 * 4));
        int sz = (row < max_rows) ? 16 : 0;
        asm volatile("cp.async.cg.shared.global [%0], [%1], 16, %2;"
                     :: "r"(daddr), "l"(src + (size_t)row * FIN + f4 * 4), "r"(sz));
    }
}

__global__ __launch_bounds__(256) void k_gemm(const float* __restrict__ x,
                                              const float* __restrict__ bias,
                                              float* __restrict__ out) {
    extern __shared__ float sm[];
    float* As[2] = { sm,                  sm + 2 * STAGE_FLOATS };
    float* Bs[2] = { sm + STAGE_FLOATS,   sm + 3 * STAGE_FLOATS };

    int tid = tid = threadIdx.x;
    int wid = tid >> 5, lane = tid & 31;
    int wm = wid >> 1, wn = wid & 1;
    int g = lane >> 2, q = lane & 3;
    int b = blockIdx.y;
    int n0 = blockIdx.x * 128;
    int max_rows = NNODES - n0;        // valid A rows in this block (<=128)

    float acc[2][8][4];
#pragma unroll
    for (int mt = 0; mt < 2; mt++)
#pragma unroll
        for (int nt = 0; nt < 8; nt++)
#pragma unroll
            for (int i = 0; i < 4; i++) acc[mt][nt][i] = 0.f;

    // chunk c: term kk=c>>1, half h=c&1 (f-range [32h, 32h+32))
    const float* terms[KPOLY];
    terms[0] = x + ((size_t)b * NNODES + n0) * FIN;
#pragma unroll
    for (int kk = 1; kk < KPOLY; kk++)
        terms[kk] = g_T + (size_t)(kk - 1) * TERM_SZ + ((size_t)b * NNODES + n0) * FIN;

    // prefetch chunk 0
    load_chunk(As[0], terms[0], max_rows);
    load_chunk(Bs[0], g_Wt, 128);
    asm volatile("cp.async.commit_group;" ::: "memory");

#pragma unroll
    for (int c = 0; c < 2 * KPOLY; c++) {
        int st = c & 1;
        if (c + 1 < 2 * KPOLY) {
            int kk = (c + 1) >> 1, h = (c + 1) & 1;
            load_chunk(As[st ^ 1], terms[kk] + h * KCH, max_rows);
            load_chunk(Bs[st ^ 1], g_Wt + (size_t)kk * FOUT * FIN + h * KCH, 128);
            asm volatile("cp.async.commit_group;" ::: "memory");
            asm volatile("cp.async.wait_group 1;" ::: "memory");
        } else {
            asm volatile("cp.async.wait_group 0;" ::: "memory");
        }
        __syncthreads();

        const float* A = As[st];
        const float* B = Bs[st];
#pragma unroll
        for (int k8 = 0; k8 < 4; k8++) {
            int kb = k8 * 8;
            uint32_t af[2][4];
#pragma unroll
            for (int mt = 0; mt < 2; mt++) {
                int r = wm * 32 + mt * 16 + g;
                af[mt][0] = __float_as_uint(A[r * ASTRIDE + kb + q]);
                af[mt][1] = __float_as_uint(A[(r + 8) * ASTRIDE + kb + q]);
                af[mt][2] = __float_as_uint(A[r * ASTRIDE + kb + q + 4]);
                af[mt][3] = __float_as_uint(A[(r + 8) * ASTRIDE + kb + q + 4]);
            }
#pragma unroll
            for (int nt = 0; nt < 8; nt++) {
                int cn = wn * 64 + nt * 8 + g;
                uint32_t b0 = __float_as_uint(B[cn * ASTRIDE + kb + q]);
                uint32_t b1 = __float_as_uint(B[cn * ASTRIDE + kb + q + 4]);
                mma_tf32_16x8x8(acc[0][nt], af[0], b0, b1);
                mma_tf32_16x8x8(acc[1][nt], af[1], b0, b1);
            }
        }
        __syncthreads();
    }

    // epilogue: bias + ReLU, pool rows {g, g^1, g^2} via shfl, pooled stores
#pragma unroll
    for (int mt = 0; mt < 2; mt++) {
#pragma unroll
        for (int half = 0; half < 2; half++) {
            int nodebase = n0 + wm * 32 + mt * 16 + half * 8 + g;
            float res[8][2];
#pragma unroll
            for (int nt = 0; nt < 8; nt++) {
                int col = wn * 64 + nt * 8 + 2 * q;
                float v0 = fmaxf(acc[mt][nt][half * 2 + 0] + __ldg(bias + col), 0.f);
                float v1 = fmaxf(acc[mt][nt][half * 2 + 1] + __ldg(bias + col + 1), 0.f);
                v0 = fmaxf(v0, __shfl_xor_sync(0xffffffffu, v0, 4));
                v0 = fmaxf(v0, __shfl_xor_sync(0xffffffffu, v0, 8));
                v1 = fmaxf(v1, __shfl_xor_sync(0xffffffffu, v1, 4));
                v1 = fmaxf(v1, __shfl_xor_sync(0xffffffffu, v1, 8));
                res[nt][0] = v0;
                res[nt][1] = v1;
            }
            if ((g & 3) == 0 && nodebase < NNODES) {
                float* op = out + ((size_t)b * NPOOL + (nodebase >> 2)) * FOUT;
#pragma unroll
                for (int nt = 0; nt < 8; nt++) {
                    int col = wn * 64 + nt * 8 + 2 * q;
                    *(float2*)(op + col) = make_float2(res[nt][0], res[nt][1]);
                }
            }
        }
    }
}

// ---------------- launch ---------------------------------------------------------
extern "C" void kernel_launch(void* const* d_in, const int* in_sizes, int n_in,
                              void* d_out, int out_size) {
    const float* x    = (const float*)d_in[0];
    const int*   rows = (const int*)d_in[1];
    const int*   cols = (const int*)d_in[2];
    const float* vals = (const float*)d_in[3];
    const float* W    = (const float*)d_in[4];
    const float* bias = (const float*)d_in[5];
    float* out = (float*)d_out;

    cudaFuncSetAttribute(k_gemm, cudaFuncAttributeMaxDynamicSharedMemorySize, SMEM_BYTES);

    // CSR build + weight transpose
    k_zero_counts<<<(NNODES + 255) / 256, 256>>>();
    k_count<<<(NEDGES + 255) / 256, 256>>>(rows);
    k_scan<<<1, 256>>>();
    k_scatter<<<(NEDGES + 255) / 256, 256>>>(rows, cols, vals);
    k_wt<<<(KPOLY * FOUT * FIN + 255) / 256, 256>>>(W);

    // Chebyshev recurrence: T1 = L x ; Tk = 2 L T(k-1) - T(k-2)
    const int spmm_blocks = (BATCH * NNODES) / 8;
    k_spmm<<<spmm_blocks, 256>>>(x, -1, 0, -2);
    k_spmm<<<spmm_blocks, 256>>>(x,  0, 1, -1);
    k_spmm<<<spmm_blocks, 256>>>(x,  1, 2,  0);
    k_spmm<<<spmm_blocks, 256>>>(x,  2, 3,  1);

    // tensor-core projection + fused epilogue
    dim3 grid((NNODES + 127) / 128, BATCH);
    k_gemm<<<grid, 256, SMEM_BYTES>>>(x, bias, out);
}

// round 5
// speedup vs baseline: 2.1033x; 1.0592x over previous
#include <cuda_runtime.h>
#include <cstdint>

#define NNODES 10000
#define NEDGES 160000
#define BATCH  32
#define FIN    64
#define KPOLY  5
#define FOUT   128
#define NPOOL  (NNODES / 4)
#define TERM_SZ ((size_t)BATCH * NNODES * FIN)

// ---------------- static device scratch (no allocations allowed) ----------------
__device__ float g_T[4 * (size_t)BATCH * NNODES * FIN];   // terms T1..T4 (T0 == x)
__device__ float g_Wt[KPOLY * FOUT * FIN];                // W transposed: [k][fo][f]
__device__ int   g_count[NNODES];
__device__ int   g_cursor[NNODES];
__device__ int   g_row_start[NNODES + 1];
__device__ int2  g_csr[NEDGES];                           // packed (col, val-bits)

// ---------------- CSR build: histogram -> scan -> permuting scatter -------------
__global__ void k_zero_counts() {
    int i = blockIdx.x * blockDim.x + threadIdx.x;
    if (i < NNODES) g_count[i] = 0;
}
__global__ void k_count(const int* __restrict__ rows) {
    int e = blockIdx.x * blockDim.x + threadIdx.x;
    if (e < NEDGES) atomicAdd(&g_count[rows[e]], 1);
}
__global__ void k_scan() {
    const int T = 256;
    const int PER = (NNODES + T - 1) / T;
    int t = threadIdx.x;
    int base = t * PER;
    int sum = 0;
    for (int i = 0; i < PER; i++) {
        int idx = base + i;
        if (idx < NNODES) sum += g_count[idx];
    }
    __shared__ int sc[T];
    sc[t] = sum;
    __syncthreads();
    for (int d = 1; d < T; d <<= 1) {
        int v = (t >= d) ? sc[t - d] : 0;
        __syncthreads();
        sc[t] += v;
        __syncthreads();
    }
    int run = sc[t] - sum;
    for (int i = 0; i < PER; i++) {
        int idx = base + i;
        if (idx < NNODES) {
            g_row_start[idx] = run;
            g_cursor[idx] = run;
            run += g_count[idx];
        }
    }
    if (t == T - 1) g_row_start[NNODES] = run;
}
__global__ void k_scatter(const int* __restrict__ rows, const int* __restrict__ cols,
                          const float* __restrict__ vals) {
    int e = blockIdx.x * blockDim.x + threadIdx.x;
    if (e < NEDGES) {
        int r = rows[e];
        int p = atomicAdd(&g_cursor[r], 1);
        g_csr[p] = make_int2(cols[e], __float_as_int(vals[e]));
    }
}

// weight transpose: g_Wt[k][fo][f] = W[f*5+k][fo]
__global__ void k_wt(const float* __restrict__ W) {
    int i = blockIdx.x * blockDim.x + threadIdx.x;
    if (i < KPOLY * FOUT * FIN) {
        int k = i / (FOUT * FIN);
        int r = i - k * FOUT * FIN;
        int fo = r / FIN;
        int f = r - fo * FIN;
        g_Wt[i] = W[(f * KPOLY + k) * FOUT + fo];
    }
}

// ---------------- gather SpMM (Chebyshev step) ----------------------------------
// One warp handles one node row for 4 batches (b, b+4, b+8, b+12); a launch
// covers 16 batches starting at b0 (two launches per term keep the per-launch
// L2 working set ~123 MB < 126 MB). Packed csr: 1 LDG.64 per edge per warp.
__global__ __launch_bounds__(256) void k_spmm(const float* __restrict__ x,
                                              int in_t, int out_t, int prev_t,
                                              int b0) {
    int w = (blockIdx.x * 256 + threadIdx.x) >> 5;
    if (w >= NNODES * 4) return;
    int r = w >> 2;                    // adjacent warps share a row: index L1 hits
    int b = b0 + (w & 3);              // batches b, b+4, b+8, b+12
    int lane = threadIdx.x & 31;
    const size_t BSTR = (size_t)4 * NNODES * FIN;

    const float* Tin = (in_t < 0) ? x : (g_T + (size_t)in_t * TERM_SZ);
    const float* base = Tin + (size_t)b * NNODES * FIN;

    int s = g_row_start[r];
    int e = g_row_start[r + 1];
    float acc[4][2];
#pragma unroll
    for (int i = 0; i < 4; i++) { acc[i][0] = 0.f; acc[i][1] = 0.f; }

    int j = s;
    for (; j + 1 < e; j += 2) {
        int2 cv0 = g_csr[j];
        int2 cv1 = g_csr[j + 1];
        size_t o0 = (size_t)cv0.x * FIN;
        size_t o1 = (size_t)cv1.x * FIN;
        float v0 = __int_as_float(cv0.y);
        float v1 = __int_as_float(cv1.y);
        float p0[4][2], p1[4][2];
#pragma unroll
        for (int i = 0; i < 4; i++) {
            const float* q0 = base + i * BSTR + o0;
            const float* q1 = base + i * BSTR + o1;
            p0[i][0] = __ldg(q0 + lane); p0[i][1] = __ldg(q0 + lane + 32);
            p1[i][0] = __ldg(q1 + lane); p1[i][1] = __ldg(q1 + lane + 32);
        }
#pragma unroll
        for (int i = 0; i < 4; i++) {
            acc[i][0] = fmaf(v0, p0[i][0], acc[i][0]);
            acc[i][1] = fmaf(v0, p0[i][1], acc[i][1]);
            acc[i][0] = fmaf(v1, p1[i][0], acc[i][0]);
            acc[i][1] = fmaf(v1, p1[i][1], acc[i][1]);
        }
    }
    if (j < e) {
        int2 cv = g_csr[j];
        size_t o = (size_t)cv.x * FIN;
        float v = __int_as_float(cv.y);
#pragma unroll
        for (int i = 0; i < 4; i++) {
            const float* q = base + i * BSTR + o;
            acc[i][0] = fmaf(v, __ldg(q + lane), acc[i][0]);
            acc[i][1] = fmaf(v, __ldg(q + lane + 32), acc[i][1]);
        }
    }

    size_t o = ((size_t)b * NNODES + r) * FIN;
    if (prev_t >= -1) {
        const float* Tp = (prev_t < 0) ? x : (g_T + (size_t)prev_t * TERM_SZ);
#pragma unroll
        for (int i = 0; i < 4; i++) {
            acc[i][0] = 2.f * acc[i][0] - Tp[o + i * BSTR + lane];
            acc[i][1] = 2.f * acc[i][1] - Tp[o + i * BSTR + lane + 32];
        }
    }
    float* dst = g_T + (size_t)out_t * TERM_SZ + o;
#pragma unroll
    for (int i = 0; i < 4; i++) {
        dst[i * BSTR + lane]      = acc[i][0];
        dst[i * BSTR + lane + 32] = acc[i][1];
    }
}

// ---------------- mma.sync tf32 projection + bias + ReLU + maxpool4 -------------
// CTA: 128 nodes x 128 fo. 8 warps (4x2), warp tile 32x64. K = 320 in 10 chunks
// of 32, cp.async double-buffered. Smem rows padded to 36 floats (conflict-free
// fragment loads AND 16B-aligned cp.async). Fragments go through cvt.rna.tf32
// (round-to-nearest) to halve the tf32 quantization error vs raw truncation.
#define KCH    32
#define ASTRIDE 36
#define STAGE_FLOATS (128 * ASTRIDE)
#define SMEM_FLOATS  (2 * 2 * STAGE_FLOATS)
#define SMEM_BYTES   (SMEM_FLOATS * 4)                  // 73728

__device__ __forceinline__ uint32_t to_tf32(float f) {
    uint32_t r;
    asm("cvt.rna.tf32.f32 %0, %1;" : "=r"(r) : "f"(f));
    return r;
}

__device__ __forceinline__ void mma_tf32_16x8x8(float* d, const uint32_t* a,
                                                uint32_t b0, uint32_t b1) {
    asm volatile(
        "mma.sync.aligned.m16n8k8.row.col.f32.tf32.tf32.f32 "
        "{%0,%1,%2,%3}, {%4,%5,%6,%7}, {%8,%9}, {%0,%1,%2,%3};"
        : "+f"(d[0]), "+f"(d[1]), "+f"(d[2]), "+f"(d[3])
        : "r"(a[0]), "r"(a[1]), "r"(a[2]), "r"(a[3]), "r"(b0), "r"(b1));
}

__device__ __forceinline__ void load_chunk(float* dst, const float* __restrict__ src,
                                           int max_rows) {
    int t = threadIdx.x;
#pragma unroll
    for (int i = 0; i < 4; i++) {
        int q = t + 256 * i;           // 0..1023 16B ops
        int row = q >> 3;              // 0..127
        int f4 = q & 7;                // 0..7
        uint32_t daddr;
        asm("{ .reg .u64 tt; cvta.to.shared.u64 tt, %1; cvt.u32.u64 %0, tt; }"
            : "=r"(daddr) : "l"(dst + row * ASTRIDE + f4 * 4));
        int sz = (row < max_rows) ? 16 : 0;
        asm volatile("cp.async.cg.shared.global [%0], [%1], 16, %2;"
                     :: "r"(daddr), "l"(src + (size_t)row * FIN + f4 * 4), "r"(sz));
    }
}

__global__ __launch_bounds__(256) void k_gemm(const float* __restrict__ x,
                                              const float* __restrict__ bias,
                                              float* __restrict__ out) {
    extern __shared__ float sm[];
    float* As[2] = { sm,                sm + 2 * STAGE_FLOATS };
    float* Bs[2] = { sm + STAGE_FLOATS, sm + 3 * STAGE_FLOATS };

    int tid = threadIdx.x;
    int wid = tid >> 5, lane = tid & 31;
    int wm = wid >> 1, wn = wid & 1;
    int g = lane >> 2, q = lane & 3;
    int b = blockIdx.y;
    int n0 = blockIdx.x * 128;
    int max_rows = NNODES - n0;

    float acc[2][8][4];
#pragma unroll
    for (int mt = 0; mt < 2; mt++)
#pragma unroll
        for (int nt = 0; nt < 8; nt++)
#pragma unroll
            for (int i = 0; i < 4; i++) acc[mt][nt][i] = 0.f;

    const float* terms[KPOLY];
    terms[0] = x + ((size_t)b * NNODES + n0) * FIN;
#pragma unroll
    for (int kk = 1; kk < KPOLY; kk++)
        terms[kk] = g_T + (size_t)(kk - 1) * TERM_SZ + ((size_t)b * NNODES + n0) * FIN;

    load_chunk(As[0], terms[0], max_rows);
    load_chunk(Bs[0], g_Wt, 128);
    asm volatile("cp.async.commit_group;" ::: "memory");

#pragma unroll
    for (int c = 0; c < 2 * KPOLY; c++) {
        int st = c & 1;
        if (c + 1 < 2 * KPOLY) {
            int kk = (c + 1) >> 1, h = (c + 1) & 1;
            load_chunk(As[st ^ 1], terms[kk] + h * KCH, max_rows);
            load_chunk(Bs[st ^ 1], g_Wt + (size_t)kk * FOUT * FIN + h * KCH, 128);
            asm volatile("cp.async.commit_group;" ::: "memory");
            asm volatile("cp.async.wait_group 1;" ::: "memory");
        } else {
            asm volatile("cp.async.wait_group 0;" ::: "memory");
        }
        __syncthreads();

        const float* A = As[st];
        const float* B = Bs[st];
#pragma unroll
        for (int k8 = 0; k8 < 4; k8++) {
            int kb = k8 * 8;
            uint32_t af[2][4];
#pragma unroll
            for (int mt = 0; mt < 2; mt++) {
                int r = wm * 32 + mt * 16 + g;
                af[mt][0] = to_tf32(A[r * ASTRIDE + kb + q]);
                af[mt][1] = to_tf32(A[(r + 8) * ASTRIDE + kb + q]);
                af[mt][2] = to_tf32(A[r * ASTRIDE + kb + q + 4]);
                af[mt][3] = to_tf32(A[(r + 8) * ASTRIDE + kb + q + 4]);
            }
#pragma unroll
            for (int nt = 0; nt < 8; nt++) {
                int cn = wn * 64 + nt * 8 + g;
                uint32_t b0 = to_tf32(B[cn * ASTRIDE + kb + q]);
                uint32_t b1 = to_tf32(B[cn * ASTRIDE + kb + q + 4]);
                mma_tf32_16x8x8(acc[0][nt], af[0], b0, b1);
                mma_tf32_16x8x8(acc[1][nt], af[1], b0, b1);
            }
        }
        __syncthreads();
    }

    // epilogue: bias + ReLU, pool rows via 2x shfl, pooled stores
#pragma unroll
    for (int mt = 0; mt < 2; mt++) {
#pragma unroll
        for (int half = 0; half < 2; half++) {
            int nodebase = n0 + wm * 32 + mt * 16 + half * 8 + g;
            float res[8][2];
#pragma unroll
            for (int nt = 0; nt < 8; nt++) {
                int col = wn * 64 + nt * 8 + 2 * q;
                float v0 = fmaxf(acc[mt][nt][half * 2 + 0] + __ldg(bias + col), 0.f);
                float v1 = fmaxf(acc[mt][nt][half * 2 + 1] + __ldg(bias + col + 1), 0.f);
                v0 = fmaxf(v0, __shfl_xor_sync(0xffffffffu, v0, 4));
                v0 = fmaxf(v0, __shfl_xor_sync(0xffffffffu, v0, 8));
                v1 = fmaxf(v1, __shfl_xor_sync(0xffffffffu, v1, 4));
                v1 = fmaxf(v1, __shfl_xor_sync(0xffffffffu, v1, 8));
                res[nt][0] = v0;
                res[nt][1] = v1;
            }
            if ((g & 3) == 0 && nodebase < NNODES) {
                float* op = out + ((size_t)b * NPOOL + (nodebase >> 2)) * FOUT;
#pragma unroll
                for (int nt = 0; nt < 8; nt++) {
                    int col = wn * 64 + nt * 8 + 2 * q;
                    *(float2*)(op + col) = make_float2(res[nt][0], res[nt][1]);
                }
            }
        }
    }
}

// ---------------- launch ---------------------------------------------------------
extern "C" void kernel_launch(void* const* d_in, const int* in_sizes, int n_in,
                              void* d_out, int out_size) {
    const float* x    = (const float*)d_in[0];
    const int*   rows = (const int*)d_in[1];
    const int*   cols = (const int*)d_in[2];
    const float* vals = (const float*)d_in[3];
    const float* W    = (const float*)d_in[4];
    const float* bias = (const float*)d_in[5];
    float* out = (float*)d_out;

    cudaFuncSetAttribute(k_gemm, cudaFuncAttributeMaxDynamicSharedMemorySize, SMEM_BYTES);

    // CSR build + weight transpose
    k_zero_counts<<<(NNODES + 255) / 256, 256>>>();
    k_count<<<(NEDGES + 255) / 256, 256>>>(rows);
    k_scan<<<1, 256>>>();
    k_scatter<<<(NEDGES + 255) / 256, 256>>>(rows, cols, vals);
    k_wt<<<(KPOLY * FOUT * FIN + 255) / 256, 256>>>(W);

    // Chebyshev recurrence: T1 = L x ; Tk = 2 L T(k-1) - T(k-2)
    // two 16-batch launches per term keep the L2 working set resident
    const int spmm_blocks = (NNODES * 4) / 8;   // 5000 blocks of 8 warps
    for (int half = 0; half < 2; half++) {
        int b0 = half * 16;
        k_spmm<<<spmm_blocks, 256>>>(x, -1, 0, -2, b0);
    }
    for (int half = 0; half < 2; half++) {
        int b0 = half * 16;
        k_spmm<<<spmm_blocks, 256>>>(x,  0, 1, -1, b0);
    }
    for (int half = 0; half < 2; half++) {
        int b0 = half * 16;
        k_spmm<<<spmm_blocks, 256>>>(x,  1, 2,  0, b0);
    }
    for (int half = 0; half < 2; half++) {
        int b0 = half * 16;
        k_spmm<<<spmm_blocks, 256>>>(x,  2, 3,  1, b0);
    }

    // tensor-core projection + fused epilogue
    dim3 grid((NNODES + 127) / 128, BATCH);
    k_gemm<<<grid, 256, SMEM_BYTES>>>(x, bias, out);
}

// round 7
// speedup vs baseline: 2.5341x; 1.2048x over previous
#include <cuda_runtime.h>
#include <cuda_fp16.h>
#include <cstdint>

#define NNODES 10000
#define NEDGES 160000
#define BATCH  32
#define FIN    64
#define KPOLY  5
#define FOUT   128
#define NPOOL  (NNODES / 4)
#define TERM_SZ ((size_t)BATCH * NNODES * FIN)
#define H2TERM  (TERM_SZ / 2)

// ---------------- static device scratch (no allocations allowed) ----------------
__device__ float    g_T[4 * (size_t)BATCH * NNODES * FIN];  // fp32 terms T1..T4
__device__ __half2  g_Th[4 * H2TERM];                       // half gather copies
__device__ __half2  g_xh[H2TERM];                           // half copy of x
__device__ uint32_t g_Wt[KPOLY * FOUT * FIN];               // W^T pre-cvt to tf32 bits
__device__ int   g_count[NNODES];
__device__ int   g_cursor[NNODES];
__device__ int   g_row_start[NNODES + 1];
__device__ int2  g_csr[NEDGES];                             // packed (col, val-bits)

__device__ __forceinline__ uint32_t to_tf32(float f) {
    uint32_t r;
    asm("cvt.rna.tf32.f32 %0, %1;" : "=r"(r) : "f"(f));
    return r;
}

// ---------------- CSR build: histogram -> scan -> permuting scatter -------------
__global__ void k_zero_counts() {
    int i = blockIdx.x * blockDim.x + threadIdx.x;
    if (i < NNODES) g_count[i] = 0;
}
__global__ void k_count(const int* __restrict__ rows) {
    int e = blockIdx.x * blockDim.x + threadIdx.x;
    if (e < NEDGES) atomicAdd(&g_count[rows[e]], 1);
}
__global__ void k_scan() {
    const int T = 256;
    const int PER = (NNODES + T - 1) / T;
    int t = threadIdx.x;
    int base = t * PER;
    int sum = 0;
    for (int i = 0; i < PER; i++) {
        int idx = base + i;
        if (idx < NNODES) sum += g_count[idx];
    }
    __shared__ int sc[T];
    sc[t] = sum;
    __syncthreads();
    for (int d = 1; d < T; d <<= 1) {
        int v = (t >= d) ? sc[t - d] : 0;
        __syncthreads();
        sc[t] += v;
        __syncthreads();
    }
    int run = sc[t] - sum;
    for (int i = 0; i < PER; i++) {
        int idx = base + i;
        if (idx < NNODES) {
            g_row_start[idx] = run;
            g_cursor[idx] = run;
            run += g_count[idx];
        }
    }
    if (t == T - 1) g_row_start[NNODES] = run;
}
__global__ void k_scatter(const int* __restrict__ rows, const int* __restrict__ cols,
                          const float* __restrict__ vals) {
    int e = blockIdx.x * blockDim.x + threadIdx.x;
    if (e < NEDGES) {
        int r = rows[e];
        int p = atomicAdd(&g_cursor[r], 1);
        g_csr[p] = make_int2(cols[e], __float_as_int(vals[e]));
    }
}

// weight transpose + tf32 pre-convert: g_Wt[k][fo][f] = tf32(W[f*5+k][fo])
__global__ void k_wt(const float* __restrict__ W) {
    int i = blockIdx.x * blockDim.x + threadIdx.x;
    if (i < KPOLY * FOUT * FIN) {
        int k = i / (FOUT * FIN);
        int r = i - k * FOUT * FIN;
        int fo = r / FIN;
        int f = r - fo * FIN;
        g_Wt[i] = to_tf32(W[(f * KPOLY + k) * FOUT + fo]);
    }
}

// x -> half2 copy (gather source for T1)
__global__ void k_xh(const float* __restrict__ x) {
    size_t i = (size_t)blockIdx.x * blockDim.x + threadIdx.x;
    if (i < H2TERM) {
        float2 f = ((const float2*)x)[i];
        g_xh[i] = __floats2half2_rn(f.x, f.y);
    }
}

// ---------------- gather SpMM (Chebyshev step), fp16 gather operands ------------
// One warp = one node row x 4 batches (b0+{0,4,8,12}-style interleave). Gather
// reads half2 rows (128 B) -> halves LTS traffic vs fp32. Output written twice:
// fp32 (recurrence + GEMM) and half2 (next gather). Two 16-batch launches per
// term keep the per-launch working set ~123 MB < L2.
__global__ __launch_bounds__(256) void k_spmm(const float* __restrict__ x,
                                              int in_t, int out_t, int prev_t,
                                              int b0) {
    int w = (blockIdx.x * 256 + threadIdx.x) >> 5;
    if (w >= NNODES * 4) return;
    int r = w >> 2;                    // adjacent warps share a row: index L1 hits
    int b = b0 + (w & 3);              // batches b, b+4, b+8, b+12
    int lane = threadIdx.x & 31;
    const size_t BSTR2 = (size_t)4 * NNODES * 32;   // 4-batch stride in pair units

    const __half2* src = (in_t < 0) ? g_xh : (g_Th + (size_t)in_t * H2TERM);
    const __half2* base = src + (size_t)b * NNODES * 32;

    int s = g_row_start[r];
    int e = g_row_start[r + 1];
    float2 acc[4];
#pragma unroll
    for (int i = 0; i < 4; i++) acc[i] = make_float2(0.f, 0.f);

    int j = s;
    for (; j + 1 < e; j += 2) {
        int2 cv0 = g_csr[j];
        int2 cv1 = g_csr[j + 1];
        size_t o0 = (size_t)cv0.x * 32;
        size_t o1 = (size_t)cv1.x * 32;
        float v0 = __int_as_float(cv0.y);
        float v1 = __int_as_float(cv1.y);
        __half2 h0[4], h1[4];
#pragma unroll
        for (int i = 0; i < 4; i++) {
            h0[i] = __ldg(base + i * BSTR2 + o0 + lane);
            h1[i] = __ldg(base + i * BSTR2 + o1 + lane);
        }
#pragma unroll
        for (int i = 0; i < 4; i++) {
            float2 f0 = __half22float2(h0[i]);
            float2 f1 = __half22float2(h1[i]);
            acc[i].x = fmaf(v0, f0.x, acc[i].x);
            acc[i].y = fmaf(v0, f0.y, acc[i].y);
            acc[i].x = fmaf(v1, f1.x, acc[i].x);
            acc[i].y = fmaf(v1, f1.y, acc[i].y);
        }
    }
    if (j < e) {
        int2 cv = g_csr[j];
        size_t o = (size_t)cv.x * 32;
        float v = __int_as_float(cv.y);
#pragma unroll
        for (int i = 0; i < 4; i++) {
            float2 f = __half22float2(__ldg(base + i * BSTR2 + o + lane));
            acc[i].x = fmaf(v, f.x, acc[i].x);
            acc[i].y = fmaf(v, f.y, acc[i].y);
        }
    }

    size_t o = ((size_t)b * NNODES + r) * 32;       // row offset in pair units
    if (prev_t >= -1) {
        const float2* Tp = (const float2*)((prev_t < 0) ? x
                            : (g_T + (size_t)prev_t * TERM_SZ));
#pragma unroll
        for (int i = 0; i < 4; i++) {
            float2 p = Tp[o + i * BSTR2 + lane];
            acc[i].x = 2.f * acc[i].x - p.x;
            acc[i].y = 2.f * acc[i].y - p.y;
        }
    }
    float2* dstf = (float2*)(g_T + (size_t)out_t * TERM_SZ);
    __half2* dsth = g_Th + (size_t)out_t * H2TERM;
#pragma unroll
    for (int i = 0; i < 4; i++) {
        dstf[o + i * BSTR2 + lane] = acc[i];
        dsth[o + i * BSTR2 + lane] = __floats2half2_rn(acc[i].x, acc[i].y);
    }
}

// ---------------- mma.sync tf32 projection + bias + ReLU + maxpool4 -------------
// CTA: 128 nodes x 128 fo. 8 warps (4x2), warp tile 32x64. K = 320 in 10 chunks
// of 32, cp.async double-buffered. Smem rows padded to 36 floats. A fragments
// cvt.rna.tf32; B already stored as tf32 bits (pre-converted in k_wt).
#define KCH    32
#define ASTRIDE 36
#define STAGE_FLOATS (128 * ASTRIDE)
#define SMEM_FLOATS  (2 * 2 * STAGE_FLOATS)
#define SMEM_BYTES   (SMEM_FLOATS * 4)                  // 73728

__device__ __forceinline__ void mma_tf32_16x8x8(float* d, const uint32_t* a,
                                                uint32_t b0, uint32_t b1) {
    asm volatile(
        "mma.sync.aligned.m16n8k8.row.col.f32.tf32.tf32.f32 "
        "{%0,%1,%2,%3}, {%4,%5,%6,%7}, {%8,%9}, {%0,%1,%2,%3};"
        : "+f"(d[0]), "+f"(d[1]), "+f"(d[2]), "+f"(d[3])
        : "r"(a[0]), "r"(a[1]), "r"(a[2]), "r"(a[3]), "r"(b0), "r"(b1));
}

__device__ __forceinline__ void load_chunk(float* dst, const float* __restrict__ src,
                                           int max_rows) {
    int t = threadIdx.x;
#pragma unroll
    for (int i = 0; i < 4; i++) {
        int q = t + 256 * i;           // 0..1023 16B ops
        int row = q >> 3;              // 0..127
        int f4 = q & 7;                // 0..7
        uint32_t daddr;
        asm("{ .reg .u64 tt; cvta.to.shared.u64 tt, %1; cvt.u32.u64 %0, tt; }"
            : "=r"(daddr) : "l"(dst + row * ASTRIDE + f4 * 4));
        int sz = (row < max_rows) ? 16 : 0;
        asm volatile("cp.async.cg.shared.global [%0], [%1], 16, %2;"
                     :: "r"(daddr), "l"(src + (size_t)row * FIN + f4 * 4), "r"(sz));
    }
}

__global__ __launch_bounds__(256) void k_gemm(const float* __restrict__ x,
                                              const float* __restrict__ bias,
                                              float* __restrict__ out) {
    extern __shared__ float sm[];
    float* As[2] = { sm,                sm + 2 * STAGE_FLOATS };
    float* Bs[2] = { sm + STAGE_FLOATS, sm + 3 * STAGE_FLOATS };

    int tid = threadIdx.x;
    int wid = tid >> 5, lane = tid & 31;
    int wm = wid >> 1, wn = wid & 1;
    int g = lane >> 2, q = lane & 3;
    int b = blockIdx.y;
    int n0 = blockIdx.x * 128;
    int max_rows = NNODES - n0;

    float acc[2][8][4];
#pragma unroll
    for (int mt = 0; mt < 2; mt++)
#pragma unroll
        for (int nt = 0; nt < 8; nt++)
#pragma unroll
            for (int i = 0; i < 4; i++) acc[mt][nt][i] = 0.f;

    const float* terms[KPOLY];
    terms[0] = x + ((size_t)b * NNODES + n0) * FIN;
#pragma unroll
    for (int kk = 1; kk < KPOLY; kk++)
        terms[kk] = g_T + (size_t)(kk - 1) * TERM_SZ + ((size_t)b * NNODES + n0) * FIN;
    const float* Wtf = (const float*)g_Wt;

    load_chunk(As[0], terms[0], max_rows);
    load_chunk(Bs[0], Wtf, 128);
    asm volatile("cp.async.commit_group;" ::: "memory");

#pragma unroll
    for (int c = 0; c < 2 * KPOLY; c++) {
        int st = c & 1;
        if (c + 1 < 2 * KPOLY) {
            int kk = (c + 1) >> 1, h = (c + 1) & 1;
            load_chunk(As[st ^ 1], terms[kk] + h * KCH, max_rows);
            load_chunk(Bs[st ^ 1], Wtf + (size_t)kk * FOUT * FIN + h * KCH, 128);
            asm volatile("cp.async.commit_group;" ::: "memory");
            asm volatile("cp.async.wait_group 1;" ::: "memory");
        } else {
            asm volatile("cp.async.wait_group 0;" ::: "memory");
        }
        __syncthreads();

        const float* A = As[st];
        const float* B = Bs[st];
#pragma unroll
        for (int k8 = 0; k8 < 4; k8++) {
            int kb = k8 * 8;
            uint32_t af[2][4];
#pragma unroll
            for (int mt = 0; mt < 2; mt++) {
                int r = wm * 32 + mt * 16 + g;
                af[mt][0] = to_tf32(A[r * ASTRIDE + kb + q]);
                af[mt][1] = to_tf32(A[(r + 8) * ASTRIDE + kb + q]);
                af[mt][2] = to_tf32(A[r * ASTRIDE + kb + q + 4]);
                af[mt][3] = to_tf32(A[(r + 8) * ASTRIDE + kb + q + 4]);
            }
#pragma unroll
            for (int nt = 0; nt < 8; nt++) {
                int cn = wn * 64 + nt * 8 + g;
                uint32_t b0 = __float_as_uint(B[cn * ASTRIDE + kb + q]);
                uint32_t b1 = __float_as_uint(B[cn * ASTRIDE + kb + q + 4]);
                mma_tf32_16x8x8(acc[0][nt], af[0], b0, b1);
                mma_tf32_16x8x8(acc[1][nt], af[1], b0, b1);
            }
        }
        __syncthreads();
    }

    // epilogue: bias + ReLU, pool rows via 2x shfl, pooled stores
#pragma unroll
    for (int mt = 0; mt < 2; mt++) {
#pragma unroll
        for (int half = 0; half < 2; half++) {
            int nodebase = n0 + wm * 32 + mt * 16 + half * 8 + g;
            float res[8][2];
#pragma unroll
            for (int nt = 0; nt < 8; nt++) {
                int col = wn * 64 + nt * 8 + 2 * q;
                float v0 = fmaxf(acc[mt][nt][half * 2 + 0] + __ldg(bias + col), 0.f);
                float v1 = fmaxf(acc[mt][nt][half * 2 + 1] + __ldg(bias + col + 1), 0.f);
                v0 = fmaxf(v0, __shfl_xor_sync(0xffffffffu, v0, 4));
                v0 = fmaxf(v0, __shfl_xor_sync(0xffffffffu, v0, 8));
                v1 = fmaxf(v1, __shfl_xor_sync(0xffffffffu, v1, 4));
                v1 = fmaxf(v1, __shfl_xor_sync(0xffffffffu, v1, 8));
                res[nt][0] = v0;
                res[nt][1] = v1;
            }
            if ((g & 3) == 0 && nodebase < NNODES) {
                float* op = out + ((size_t)b * NPOOL + (nodebase >> 2)) * FOUT;
#pragma unroll
                for (int nt = 0; nt < 8; nt++) {
                    int col = wn * 64 + nt * 8 + 2 * q;
                    *(float2*)(op + col) = make_float2(res[nt][0], res[nt][1]);
                }
            }
        }
    }
}

// ---------------- launch ---------------------------------------------------------
extern "C" void kernel_launch(void* const* d_in, const int* in_sizes, int n_in,
                              void* d_out, int out_size) {
    const float* x    = (const float*)d_in[0];
    const int*   rows = (const int*)d_in[1];
    const int*   cols = (const int*)d_in[2];
    const float* vals = (const float*)d_in[3];
    const float* W    = (const float*)d_in[4];
    const float* bias = (const float*)d_in[5];
    float* out = (float*)d_out;

    cudaFuncSetAttribute(k_gemm, cudaFuncAttributeMaxDynamicSharedMemorySize, SMEM_BYTES);

    // CSR build + weight transpose/cvt + half copy of x
    k_zero_counts<<<(NNODES + 255) / 256, 256>>>();
    k_count<<<(NEDGES + 255) / 256, 256>>>(rows);
    k_scan<<<1, 256>>>();
    k_scatter<<<(NEDGES + 255) / 256, 256>>>(rows, cols, vals);
    k_wt<<<(KPOLY * FOUT * FIN + 255) / 256, 256>>>(W);
    k_xh<<<(int)((H2TERM + 255) / 256), 256>>>(x);

    // Chebyshev recurrence: T1 = L x ; Tk = 2 L T(k-1) - T(k-2)
    const int spmm_blocks = (NNODES * 4) / 8;   // 5000 blocks of 8 warps
    for (int half = 0; half < 2; half++)
        k_spmm<<<spmm_blocks, 256>>>(x, -1, 0, -2, half * 16);
    for (int half = 0; half < 2; half++)
        k_spmm<<<spmm_blocks, 256>>>(x,  0, 1, -1, half * 16);
    for (int half = 0; half < 2; half++)
        k_spmm<<<spmm_blocks, 256>>>(x,  1, 2,  0, half * 16);
    for (int half = 0; half < 2; half++)
        k_spmm<<<spmm_blocks, 256>>>(x,  2, 3,  1, half * 16);

    // tensor-core projection + fused epilogue
    dim3 grid((NNODES + 127) / 128, BATCH);
    k_gemm<<<grid, 256, SMEM_BYTES>>>(x, bias, out);
}

// round 8
// speedup vs baseline: 3.2598x; 1.2864x over previous
#include <cuda_runtime.h>
#include <cuda_fp16.h>
#include <cstdint>

#define NNODES 10000
#define NEDGES 160000
#define BATCH  32
#define FIN    64
#define KPOLY  5
#define FOUT   128
#define NPOOL  (NNODES / 4)
#define TERM_SZ ((size_t)BATCH * NNODES * FIN)

// ---------------- static device scratch (no allocations allowed) ----------------
__device__ float   g_T[4 * (size_t)BATCH * NNODES * FIN]; // fp32 recurrence carrier
__device__ __half  g_Th[4 * (size_t)BATCH * NNODES * FIN];// half copies (gather+GEMM)
__device__ __half  g_xh[(size_t)BATCH * NNODES * FIN];    // half copy of x
__device__ __half  g_Wh[KPOLY * FOUT * FIN];              // W^T in half: [k][fo][f]
__device__ int   g_count[NNODES];
__device__ int   g_cursor[NNODES];
__device__ int   g_row_start[NNODES + 1];
__device__ int2  g_csr[NEDGES];                           // packed (col, val-bits)

// ---------------- CSR build: histogram -> scan -> permuting scatter -------------
__global__ void k_zero_counts() {
    int i = blockIdx.x * blockDim.x + threadIdx.x;
    if (i < NNODES) g_count[i] = 0;
}
__global__ void k_count(const int* __restrict__ rows) {
    int e = blockIdx.x * blockDim.x + threadIdx.x;
    if (e < NEDGES) atomicAdd(&g_count[rows[e]], 1);
}
__global__ void k_scan() {
    const int T = 256;
    const int PER = (NNODES + T - 1) / T;
    int t = threadIdx.x;
    int base = t * PER;
    int sum = 0;
    for (int i = 0; i < PER; i++) {
        int idx = base + i;
        if (idx < NNODES) sum += g_count[idx];
    }
    __shared__ int sc[T];
    sc[t] = sum;
    __syncthreads();
    for (int d = 1; d < T; d <<= 1) {
        int v = (t >= d) ? sc[t - d] : 0;
        __syncthreads();
        sc[t] += v;
        __syncthreads();
    }
    int run = sc[t] - sum;
    for (int i = 0; i < PER; i++) {
        int idx = base + i;
        if (idx < NNODES) {
            g_row_start[idx] = run;
            g_cursor[idx] = run;
            run += g_count[idx];
        }
    }
    if (t == T - 1) g_row_start[NNODES] = run;
}
__global__ void k_scatter(const int* __restrict__ rows, const int* __restrict__ cols,
                          const float* __restrict__ vals) {
    int e = blockIdx.x * blockDim.x + threadIdx.x;
    if (e < NEDGES) {
        int r = rows[e];
        int p = atomicAdd(&g_cursor[r], 1);
        g_csr[p] = make_int2(cols[e], __float_as_int(vals[e]));
    }
}

// weight transpose + half convert: g_Wh[k][fo][f] = half(W[f*5+k][fo])
__global__ void k_wh(const float* __restrict__ W) {
    int i = blockIdx.x * blockDim.x + threadIdx.x;
    if (i < KPOLY * FOUT * FIN) {
        int k = i / (FOUT * FIN);
        int r = i - k * FOUT * FIN;
        int fo = r / FIN;
        int f = r - fo * FIN;
        g_Wh[i] = __float2half(W[(f * KPOLY + k) * FOUT + fo]);
    }
}

// x -> half copy
__global__ void k_xh(const float* __restrict__ x) {
    size_t i = (size_t)blockIdx.x * blockDim.x + threadIdx.x;
    if (i < TERM_SZ / 2) {
        float2 f = ((const float2*)x)[i];
        ((__half2*)g_xh)[i] = __floats2half2_rn(f.x, f.y);
    }
}

// ---------------- gather SpMM (Chebyshev step), fp16 gather operands ------------
// One CTA = one node row, 8 warps = 8 batch groups x 4 batches each. All warps
// share the CSR row segment (index loads L1-hit). Gather reads half2 rows;
// recurrence carrier kept fp32 with .cs streaming hints (evict-first) so L2
// retains the half gather source; half output written default-cached (it is the
// next term's gather source).
__global__ __launch_bounds__(256) void k_spmm(const float* __restrict__ x,
                                              int in_t, int out_t, int prev_t) {
    int r = blockIdx.x;                 // node row
    int grp = threadIdx.x >> 5;         // 0..7
    int lane = threadIdx.x & 31;
    const size_t BSTR2 = (size_t)8 * NNODES * 32;   // 8-batch stride (half2 units)

    const __half2* src = (const __half2*)((in_t < 0) ? g_xh
                          : g_Th + (size_t)in_t * TERM_SZ);
    const __half2* base = src + (size_t)grp * NNODES * 32;

    int s = g_row_start[r];
    int e = g_row_start[r + 1];
    float2 acc[4];
#pragma unroll
    for (int i = 0; i < 4; i++) acc[i] = make_float2(0.f, 0.f);

    int j = s;
    for (; j + 1 < e; j += 2) {
        int2 cv0 = g_csr[j];
        int2 cv1 = g_csr[j + 1];
        size_t o0 = (size_t)cv0.x * 32;
        size_t o1 = (size_t)cv1.x * 32;
        float v0 = __int_as_float(cv0.y);
        float v1 = __int_as_float(cv1.y);
        __half2 h0[4], h1[4];
#pragma unroll
        for (int i = 0; i < 4; i++) {
            h0[i] = __ldg(base + i * BSTR2 + o0 + lane);
            h1[i] = __ldg(base + i * BSTR2 + o1 + lane);
        }
#pragma unroll
        for (int i = 0; i < 4; i++) {
            float2 f0 = __half22float2(h0[i]);
            float2 f1 = __half22float2(h1[i]);
            acc[i].x = fmaf(v0, f0.x, acc[i].x);
            acc[i].y = fmaf(v0, f0.y, acc[i].y);
            acc[i].x = fmaf(v1, f1.x, acc[i].x);
            acc[i].y = fmaf(v1, f1.y, acc[i].y);
        }
    }
    if (j < e) {
        int2 cv = g_csr[j];
        size_t o = (size_t)cv.x * 32;
        float v = __int_as_float(cv.y);
#pragma unroll
        for (int i = 0; i < 4; i++) {
            float2 f = __half22float2(__ldg(base + i * BSTR2 + o + lane));
            acc[i].x = fmaf(v, f.x, acc[i].x);
            acc[i].y = fmaf(v, f.y, acc[i].y);
        }
    }

    // per-batch offset in float2/half2 units: batch b = grp + i*8
    size_t o = ((size_t)grp * NNODES + r) * 32 + lane;
    if (prev_t >= -1) {
        const float2* Tp = (const float2*)((prev_t < 0) ? x
                            : (g_T + (size_t)prev_t * TERM_SZ));
#pragma unroll
        for (int i = 0; i < 4; i++) {
            float2 p = __ldcs(Tp + o + i * BSTR2);   // streaming read
            acc[i].x = 2.f * acc[i].x - p.x;
            acc[i].y = 2.f * acc[i].y - p.y;
        }
    }
    float2*  dstf = (float2*)(g_T + (size_t)out_t * TERM_SZ);
    __half2* dsth = (__half2*)(g_Th + (size_t)out_t * TERM_SZ);
#pragma unroll
    for (int i = 0; i < 4; i++) {
        __stcs(dstf + o + i * BSTR2, acc[i]);        // streaming write (read once)
        dsth[o + i * BSTR2] = __floats2half2_rn(acc[i].x, acc[i].y);
    }
}

// ---------------- fp16 mma projection + bias + ReLU + maxpool4 ------------------
// CTA: 128 nodes x 128 fo, 8 warps (4x2), warp tile 32x64. K = 320 in 5 chunks
// of 64 (one per term), cp.async double-buffered, all operands half.
// Smem rows: 64 halves padded to 72 (144 B = 9x16 B): conflict-free fragments.
#define HSTR 72
#define STAGE_BYTES (128 * HSTR * 2)                 // 18432 per matrix per stage
#define SMEM_BYTES  (4 * STAGE_BYTES)                // 73728

__device__ __forceinline__ void mma_f16(float* d, const uint32_t* a,
                                        uint32_t b0, uint32_t b1) {
    asm volatile(
        "mma.sync.aligned.m16n8k16.row.col.f32.f16.f16.f32 "
        "{%0,%1,%2,%3}, {%4,%5,%6,%7}, {%8,%9}, {%0,%1,%2,%3};"
        : "+f"(d[0]), "+f"(d[1]), "+f"(d[2]), "+f"(d[3])
        : "r"(a[0]), "r"(a[1]), "r"(a[2]), "r"(a[3]), "r"(b0), "r"(b1));
}

// 128 rows x 64 half (128 B/row) -> smem rows of 144 B; rows >= max_rows zeroed
__device__ __forceinline__ void load_chunk(__half* dst, const __half* __restrict__ src,
                                           int max_rows) {
    int t = threadIdx.x;
#pragma unroll
    for (int i = 0; i < 4; i++) {
        int q = t + 256 * i;           // 0..1023 16B ops
        int row = q >> 3;              // 0..127
        int f4 = q & 7;                // 0..7
        uint32_t daddr;
        asm("{ .reg .u64 tt; cvta.to.shared.u64 tt, %1; cvt.u32.u64 %0, tt; }"
            : "=r"(daddr) : "l"(dst + row * HSTR + f4 * 8));
        int sz = (row < max_rows) ? 16 : 0;
        asm volatile("cp.async.cg.shared.global [%0], [%1], 16, %2;"
                     :: "r"(daddr), "l"(src + (size_t)row * FIN + f4 * 8), "r"(sz));
    }
}

__global__ __launch_bounds__(256) void k_gemm(const float* __restrict__ bias,
                                              float* __restrict__ out) {
    extern __shared__ __half sm[];
    __half* As[2] = { sm,                 sm + 2 * 128 * HSTR };
    __half* Bs[2] = { sm + 128 * HSTR,    sm + 3 * 128 * HSTR };

    int tid = threadIdx.x;
    int wid = tid >> 5, lane = tid & 31;
    int wm = wid >> 1, wn = wid & 1;
    int g = lane >> 2, q = lane & 3;
    int b = blockIdx.y;
    int n0 = blockIdx.x * 128;
    int max_rows = NNODES - n0;

    float acc[2][8][4];
#pragma unroll
    for (int mt = 0; mt < 2; mt++)
#pragma unroll
        for (int nt = 0; nt < 8; nt++)
#pragma unroll
            for (int i = 0; i < 4; i++) acc[mt][nt][i] = 0.f;

    const __half* terms[KPOLY];
    terms[0] = g_xh + ((size_t)b * NNODES + n0) * FIN;
#pragma unroll
    for (int kk = 1; kk < KPOLY; kk++)
        terms[kk] = g_Th + (size_t)(kk - 1) * TERM_SZ + ((size_t)b * NNODES + n0) * FIN;

    load_chunk(As[0], terms[0], max_rows);
    load_chunk(Bs[0], g_Wh, 128);
    asm volatile("cp.async.commit_group;" ::: "memory");

#pragma unroll
    for (int c = 0; c < KPOLY; c++) {
        int st = c & 1;
        if (c + 1 < KPOLY) {
            load_chunk(As[st ^ 1], terms[c + 1], max_rows);
            load_chunk(Bs[st ^ 1], g_Wh + (size_t)(c + 1) * FOUT * FIN, 128);
            asm volatile("cp.async.commit_group;" ::: "memory");
            asm volatile("cp.async.wait_group 1;" ::: "memory");
        } else {
            asm volatile("cp.async.wait_group 0;" ::: "memory");
        }
        __syncthreads();

        const __half* A = As[st];
        const __half* B = Bs[st];
#pragma unroll
        for (int k16 = 0; k16 < 4; k16++) {
            int kb = k16 * 16;
            uint32_t af[2][4];
#pragma unroll
            for (int mt = 0; mt < 2; mt++) {
                int r = wm * 32 + mt * 16 + g;
                af[mt][0] = *(const uint32_t*)(A + r * HSTR + kb + 2 * q);
                af[mt][1] = *(const uint32_t*)(A + (r + 8) * HSTR + kb + 2 * q);
                af[mt][2] = *(const uint32_t*)(A + r * HSTR + kb + 8 + 2 * q);
                af[mt][3] = *(const uint32_t*)(A + (r + 8) * HSTR + kb + 8 + 2 * q);
            }
#pragma unroll
            for (int nt = 0; nt < 8; nt++) {
                int cn = wn * 64 + nt * 8 + g;
                uint32_t b0 = *(const uint32_t*)(B + cn * HSTR + kb + 2 * q);
                uint32_t b1 = *(const uint32_t*)(B + cn * HSTR + kb + 8 + 2 * q);
                mma_f16(acc[0][nt], af[0], b0, b1);
                mma_f16(acc[1][nt], af[1], b0, b1);
            }
        }
        __syncthreads();
    }

    // epilogue: bias + ReLU, maxpool-4 over fragment rows via 2x shfl, pooled stores
#pragma unroll
    for (int mt = 0; mt < 2; mt++) {
#pragma unroll
        for (int half = 0; half < 2; half++) {
            int nodebase = n0 + wm * 32 + mt * 16 + half * 8 + g;
            float res[8][2];
#pragma unroll
            for (int nt = 0; nt < 8; nt++) {
                int col = wn * 64 + nt * 8 + 2 * q;
                float v0 = fmaxf(acc[mt][nt][half * 2 + 0] + __ldg(bias + col), 0.f);
                float v1 = fmaxf(acc[mt][nt][half * 2 + 1] + __ldg(bias + col + 1), 0.f);
                v0 = fmaxf(v0, __shfl_xor_sync(0xffffffffu, v0, 4));
                v0 = fmaxf(v0, __shfl_xor_sync(0xffffffffu, v0, 8));
                v1 = fmaxf(v1, __shfl_xor_sync(0xffffffffu, v1, 4));
                v1 = fmaxf(v1, __shfl_xor_sync(0xffffffffu, v1, 8));
                res[nt][0] = v0;
                res[nt][1] = v1;
            }
            if ((g & 3) == 0 && nodebase < NNODES) {
                float* op = out + ((size_t)b * NPOOL + (nodebase >> 2)) * FOUT;
#pragma unroll
                for (int nt = 0; nt < 8; nt++) {
                    int col = wn * 64 + nt * 8 + 2 * q;
                    *(float2*)(op + col) = make_float2(res[nt][0], res[nt][1]);
                }
            }
        }
    }
}

// ---------------- launch ---------------------------------------------------------
extern "C" void kernel_launch(void* const* d_in, const int* in_sizes, int n_in,
                              void* d_out, int out_size) {
    const float* x    = (const float*)d_in[0];
    const int*   rows = (const int*)d_in[1];
    const int*   cols = (const int*)d_in[2];
    const float* vals = (const float*)d_in[3];
    const float* W    = (const float*)d_in[4];
    const float* bias = (const float*)d_in[5];
    float* out = (float*)d_out;

    cudaFuncSetAttribute(k_gemm, cudaFuncAttributeMaxDynamicSharedMemorySize, SMEM_BYTES);

    // CSR build + weight/x half conversion
    k_zero_counts<<<(NNODES + 255) / 256, 256>>>();
    k_count<<<(NEDGES + 255) / 256, 256>>>(rows);
    k_scan<<<1, 256>>>();
    k_scatter<<<(NEDGES + 255) / 256, 256>>>(rows, cols, vals);
    k_wh<<<(KPOLY * FOUT * FIN + 255) / 256, 256>>>(W);
    k_xh<<<(int)((TERM_SZ / 2 + 255) / 256), 256>>>(x);

    // Chebyshev recurrence: T1 = L x ; Tk = 2 L T(k-1) - T(k-2)
    k_spmm<<<NNODES, 256>>>(x, -1, 0, -2);
    k_spmm<<<NNODES, 256>>>(x,  0, 1, -1);
    k_spmm<<<NNODES, 256>>>(x,  1, 2,  0);
    k_spmm<<<NNODES, 256>>>(x,  2, 3,  1);

    // fp16 tensor-core projection + fused epilogue
    dim3 grid((NNODES + 127) / 128, BATCH);
    k_gemm<<<grid, 256, SMEM_BYTES>>>(bias, out);
}

// round 9
// speedup vs baseline: 3.6259x; 1.1123x over previous
#include <cuda_runtime.h>
#include <cuda_fp16.h>
#include <cstdint>

#define NNODES 10000
#define NEDGES 160000
#define BATCH  32
#define FIN    64
#define KPOLY  5
#define FOUT   128
#define NPOOL  (NNODES / 4)
#define TERM_SZ ((size_t)BATCH * NNODES * FIN)

// ---------------- static device scratch (no allocations allowed) ----------------
__device__ __half  g_Th[4 * (size_t)BATCH * NNODES * FIN];// fp16 terms T1..T4
__device__ __half  g_xh[(size_t)BATCH * NNODES * FIN];    // fp16 copy of x (= T0)
__device__ __half  g_Wh[KPOLY * FOUT * FIN];              // W^T in half: [k][fo][f]
__device__ int   g_count[NNODES];
__device__ int   g_cursor[NNODES];
__device__ int   g_row_start[NNODES + 1];
__device__ int2  g_csr[NEDGES];                           // packed (col, val-bits)

// ---------------- CSR build: histogram -> scan -> permuting scatter -------------
__global__ void k_zero_counts() {
    int i = blockIdx.x * blockDim.x + threadIdx.x;
    if (i < NNODES) g_count[i] = 0;
}
__global__ void k_count(const int* __restrict__ rows) {
    int e = blockIdx.x * blockDim.x + threadIdx.x;
    if (e < NEDGES) atomicAdd(&g_count[rows[e]], 1);
}
__global__ void k_scan() {
    const int T = 256;
    const int PER = (NNODES + T - 1) / T;
    int t = threadIdx.x;
    int base = t * PER;
    int sum = 0;
    for (int i = 0; i < PER; i++) {
        int idx = base + i;
        if (idx < NNODES) sum += g_count[idx];
    }
    __shared__ int sc[T];
    sc[t] = sum;
    __syncthreads();
    for (int d = 1; d < T; d <<= 1) {
        int v = (t >= d) ? sc[t - d] : 0;
        __syncthreads();
        sc[t] += v;
        __syncthreads();
    }
    int run = sc[t] - sum;
    for (int i = 0; i < PER; i++) {
        int idx = base + i;
        if (idx < NNODES) {
            g_row_start[idx] = run;
            g_cursor[idx] = run;
            run += g_count[idx];
        }
    }
    if (t == T - 1) g_row_start[NNODES] = run;
}
__global__ void k_scatter(const int* __restrict__ rows, const int* __restrict__ cols,
                          const float* __restrict__ vals) {
    int e = blockIdx.x * blockDim.x + threadIdx.x;
    if (e < NEDGES) {
        int r = rows[e];
        int p = atomicAdd(&g_cursor[r], 1);
        g_csr[p] = make_int2(cols[e], __float_as_int(vals[e]));
    }
}

// weight transpose + half convert: g_Wh[k][fo][f] = half(W[f*5+k][fo])
__global__ void k_wh(const float* __restrict__ W) {
    int i = blockIdx.x * blockDim.x + threadIdx.x;
    if (i < KPOLY * FOUT * FIN) {
        int k = i / (FOUT * FIN);
        int r = i - k * FOUT * FIN;
        int fo = r / FIN;
        int f = r - fo * FIN;
        g_Wh[i] = __float2half(W[(f * KPOLY + k) * FOUT + fo]);
    }
}

// x -> half copy
__global__ void k_xh(const float* __restrict__ x) {
    size_t i = (size_t)blockIdx.x * blockDim.x + threadIdx.x;
    if (i < TERM_SZ / 2) {
        float2 f = ((const float2*)x)[i];
        ((__half2*)g_xh)[i] = __floats2half2_rn(f.x, f.y);
    }
}

// ---------------- gather SpMM (Chebyshev step), all-fp16 terms ------------------
// One CTA = one node row, 8 warps = 8 batch groups x 4 batches each. All warps
// share the CSR row segment (index loads L1-hit). Gather reads half2 rows;
// accumulation in fp32; recurrence prev read as half; single half2 output.
__global__ __launch_bounds__(256) void k_spmm(int in_t, int out_t, int prev_t) {
    int r = blockIdx.x;                 // node row
    int grp = threadIdx.x >> 5;         // 0..7
    int lane = threadIdx.x & 31;
    const size_t BSTR2 = (size_t)8 * NNODES * 32;   // 8-batch stride (half2 units)

    const __half2* src = (const __half2*)((in_t < 0) ? g_xh
                          : g_Th + (size_t)in_t * TERM_SZ);
    const __half2* base = src + (size_t)grp * NNODES * 32;

    int s = g_row_start[r];
    int e = g_row_start[r + 1];
    float2 acc[4];
#pragma unroll
    for (int i = 0; i < 4; i++) acc[i] = make_float2(0.f, 0.f);

    int j = s;
    for (; j + 3 < e; j += 4) {                      // 4-edge unroll: 16 LDG in flight
        int2 cv[4];
        size_t off[4];
        float v[4];
#pragma unroll
        for (int u = 0; u < 4; u++) {
            cv[u] = g_csr[j + u];
            off[u] = (size_t)cv[u].x * 32;
            v[u] = __int_as_float(cv[u].y);
        }
        __half2 h[4][4];
#pragma unroll
        for (int u = 0; u < 4; u++)
#pragma unroll
            for (int i = 0; i < 4; i++)
                h[u][i] = __ldg(base + i * BSTR2 + off[u] + lane);
#pragma unroll
        for (int u = 0; u < 4; u++)
#pragma unroll
            for (int i = 0; i < 4; i++) {
                float2 f = __half22float2(h[u][i]);
                acc[i].x = fmaf(v[u], f.x, acc[i].x);
                acc[i].y = fmaf(v[u], f.y, acc[i].y);
            }
    }
    for (; j < e; j++) {
        int2 cv = g_csr[j];
        size_t o = (size_t)cv.x * 32;
        float v = __int_as_float(cv.y);
#pragma unroll
        for (int i = 0; i < 4; i++) {
            float2 f = __half22float2(__ldg(base + i * BSTR2 + o + lane));
            acc[i].x = fmaf(v, f.x, acc[i].x);
            acc[i].y = fmaf(v, f.y, acc[i].y);
        }
    }

    // per-batch offset in half2 units: batch b = grp + i*8
    size_t o = ((size_t)grp * NNODES + r) * 32 + lane;
    if (prev_t >= -1) {
        const __half2* Tp = (const __half2*)((prev_t < 0) ? g_xh
                             : g_Th + (size_t)prev_t * TERM_SZ);
#pragma unroll
        for (int i = 0; i < 4; i++) {
            float2 p = __half22float2(__ldg(Tp + o + i * BSTR2));
            acc[i].x = 2.f * acc[i].x - p.x;
            acc[i].y = 2.f * acc[i].y - p.y;
        }
    }
    __half2* dsth = (__half2*)(g_Th + (size_t)out_t * TERM_SZ);
#pragma unroll
    for (int i = 0; i < 4; i++)
        dsth[o + i * BSTR2] = __floats2half2_rn(acc[i].x, acc[i].y);
}

// ---------------- fp16 mma projection + bias + ReLU + maxpool4 ------------------
// CTA: 128 nodes x 128 fo, 8 warps (4x2), warp tile 32x64. K = 320 in 5 chunks
// of 64 (one per term), cp.async double-buffered, all operands half.
// Smem rows: 64 halves padded to 72 (144 B = 9x16 B): conflict-free fragments.
#define HSTR 72
#define STAGE_BYTES (128 * HSTR * 2)                 // 18432 per matrix per stage
#define SMEM_BYTES  (4 * STAGE_BYTES)                // 73728

__device__ __forceinline__ void mma_f16(float* d, const uint32_t* a,
                                        uint32_t b0, uint32_t b1) {
    asm volatile(
        "mma.sync.aligned.m16n8k16.row.col.f32.f16.f16.f32 "
        "{%0,%1,%2,%3}, {%4,%5,%6,%7}, {%8,%9}, {%0,%1,%2,%3};"
        : "+f"(d[0]), "+f"(d[1]), "+f"(d[2]), "+f"(d[3])
        : "r"(a[0]), "r"(a[1]), "r"(a[2]), "r"(a[3]), "r"(b0), "r"(b1));
}

// 128 rows x 64 half (128 B/row) -> smem rows of 144 B; rows >= max_rows zeroed
__device__ __forceinline__ void load_chunk(__half* dst, const __half* __restrict__ src,
                                           int max_rows) {
    int t = threadIdx.x;
#pragma unroll
    for (int i = 0; i < 4; i++) {
        int q = t + 256 * i;           // 0..1023 16B ops
        int row = q >> 3;              // 0..127
        int f4 = q & 7;                // 0..7
        uint32_t daddr;
        asm("{ .reg .u64 tt; cvta.to.shared.u64 tt, %1; cvt.u32.u64 %0, tt; }"
            : "=r"(daddr) : "l"(dst + row * HSTR + f4 * 8));
        int sz = (row < max_rows) ? 16 : 0;
        asm volatile("cp.async.cg.shared.global [%0], [%1], 16, %2;"
                     :: "r"(daddr), "l"(src + (size_t)row * FIN + f4 * 8), "r"(sz));
    }
}

__global__ __launch_bounds__(256) void k_gemm(const float* __restrict__ bias,
                                              float* __restrict__ out) {
    extern __shared__ __half sm[];
    __half* As[2] = { sm,                 sm + 2 * 128 * HSTR };
    __half* Bs[2] = { sm + 128 * HSTR,    sm + 3 * 128 * HSTR };

    int tid = threadIdx.x;
    int wid = tid >> 5, lane = tid & 31;
    int wm = wid >> 1, wn = wid & 1;
    int g = lane >> 2, q = lane & 3;
    int b = blockIdx.y;
    int n0 = blockIdx.x * 128;
    int max_rows = NNODES - n0;

    float acc[2][8][4];
#pragma unroll
    for (int mt = 0; mt < 2; mt++)
#pragma unroll
        for (int nt = 0; nt < 8; nt++)
#pragma unroll
            for (int i = 0; i < 4; i++) acc[mt][nt][i] = 0.f;

    const __half* terms[KPOLY];
    terms[0] = g_xh + ((size_t)b * NNODES + n0) * FIN;
#pragma unroll
    for (int kk = 1; kk < KPOLY; kk++)
        terms[kk] = g_Th + (size_t)(kk - 1) * TERM_SZ + ((size_t)b * NNODES + n0) * FIN;

    load_chunk(As[0], terms[0], max_rows);
    load_chunk(Bs[0], g_Wh, 128);
    asm volatile("cp.async.commit_group;" ::: "memory");

#pragma unroll
    for (int c = 0; c < KPOLY; c++) {
        int st = c & 1;
        if (c + 1 < KPOLY) {
            load_chunk(As[st ^ 1], terms[c + 1], max_rows);
            load_chunk(Bs[st ^ 1], g_Wh + (size_t)(c + 1) * FOUT * FIN, 128);
            asm volatile("cp.async.commit_group;" ::: "memory");
            asm volatile("cp.async.wait_group 1;" ::: "memory");
        } else {
            asm volatile("cp.async.wait_group 0;" ::: "memory");
        }
        __syncthreads();

        const __half* A = As[st];
        const __half* B = Bs[st];
#pragma unroll
        for (int k16 = 0; k16 < 4; k16++) {
            int kb = k16 * 16;
            uint32_t af[2][4];
#pragma unroll
            for (int mt = 0; mt < 2; mt++) {
                int r = wm * 32 + mt * 16 + g;
                af[mt][0] = *(const uint32_t*)(A + r * HSTR + kb + 2 * q);
                af[mt][1] = *(const uint32_t*)(A + (r + 8) * HSTR + kb + 2 * q);
                af[mt][2] = *(const uint32_t*)(A + r * HSTR + kb + 8 + 2 * q);
                af[mt][3] = *(const uint32_t*)(A + (r + 8) * HSTR + kb + 8 + 2 * q);
            }
#pragma unroll
            for (int nt = 0; nt < 8; nt++) {
                int cn = wn * 64 + nt * 8 + g;
                uint32_t b0 = *(const uint32_t*)(B + cn * HSTR + kb + 2 * q);
                uint32_t b1 = *(const uint32_t*)(B + cn * HSTR + kb + 8 + 2 * q);
                mma_f16(acc[0][nt], af[0], b0, b1);
                mma_f16(acc[1][nt], af[1], b0, b1);
            }
        }
        __syncthreads();
    }

    // epilogue: bias + ReLU, maxpool-4 over fragment rows via 2x shfl, pooled stores
#pragma unroll
    for (int mt = 0; mt < 2; mt++) {
#pragma unroll
        for (int half = 0; half < 2; half++) {
            int nodebase = n0 + wm * 32 + mt * 16 + half * 8 + g;
            float res[8][2];
#pragma unroll
            for (int nt = 0; nt < 8; nt++) {
                int col = wn * 64 + nt * 8 + 2 * q;
                float v0 = fmaxf(acc[mt][nt][half * 2 + 0] + __ldg(bias + col), 0.f);
                float v1 = fmaxf(acc[mt][nt][half * 2 + 1] + __ldg(bias + col + 1), 0.f);
                v0 = fmaxf(v0, __shfl_xor_sync(0xffffffffu, v0, 4));
                v0 = fmaxf(v0, __shfl_xor_sync(0xffffffffu, v0, 8));
                v1 = fmaxf(v1, __shfl_xor_sync(0xffffffffu, v1, 4));
                v1 = fmaxf(v1, __shfl_xor_sync(0xffffffffu, v1, 8));
                res[nt][0] = v0;
                res[nt][1] = v1;
            }
            if ((g & 3) == 0 && nodebase < NNODES) {
                float* op = out + ((size_t)b * NPOOL + (nodebase >> 2)) * FOUT;
#pragma unroll
                for (int nt = 0; nt < 8; nt++) {
                    int col = wn * 64 + nt * 8 + 2 * q;
                    *(float2*)(op + col) = make_float2(res[nt][0], res[nt][1]);
                }
            }
        }
    }
}

// ---------------- launch ---------------------------------------------------------
extern "C" void kernel_launch(void* const* d_in, const int* in_sizes, int n_in,
                              void* d_out, int out_size) {
    const float* x    = (const float*)d_in[0];
    const int*   rows = (const int*)d_in[1];
    const int*   cols = (const int*)d_in[2];
    const float* vals = (const float*)d_in[3];
    const float* W    = (const float*)d_in[4];
    const float* bias = (const float*)d_in[5];
    float* out = (float*)d_out;

    cudaFuncSetAttribute(k_gemm, cudaFuncAttributeMaxDynamicSharedMemorySize, SMEM_BYTES);

    // CSR build + weight/x half conversion
    k_zero_counts<<<(NNODES + 255) / 256, 256>>>();
    k_count<<<(NEDGES + 255) / 256, 256>>>(rows);
    k_scan<<<1, 256>>>();
    k_scatter<<<(NEDGES + 255) / 256, 256>>>(rows, cols, vals);
    k_wh<<<(KPOLY * FOUT * FIN + 255) / 256, 256>>>(W);
    k_xh<<<(int)((TERM_SZ / 2 + 255) / 256), 256>>>(x);

    // Chebyshev recurrence: T1 = L x ; Tk = 2 L T(k-1) - T(k-2)
    k_spmm<<<NNODES, 256>>>(-1, 0, -2);
    k_spmm<<<NNODES, 256>>>( 0, 1, -1);
    k_spmm<<<NNODES, 256>>>( 1, 2,  0);
    k_spmm<<<NNODES, 256>>>( 2, 3,  1);

    // fp16 tensor-core projection + fused epilogue
    dim3 grid((NNODES + 127) / 128, BATCH);
    k_gemm<<<grid, 256, SMEM_BYTES>>>(bias, out);
}